// round 5
// baseline (speedup 1.0000x reference)
#include <cuda_runtime.h>

#define B_    256
#define T_    4096
#define TWO_N 16
#define H_    64
#define P_    144
#define TBL   256
#define TPB   256
#define CHUNKS (T_/TPB)      // 16
#define NBLK  (B_*CHUNKS)    // 4096
#define SUPB  40             // supervised-loss blocks (40*1024 = 40960 elems)

// fp32 table row i: 32 floats = (lat_0,dlat_0,...,lat_15,dlat_15) at t=i/TBL.
// (TBL+1)*128 B = 32.9 KB -> L1-resident (protected from stream by __ldcs).
__device__ float g_table[TBL + 1][32];
__device__ float g_pd[NBLK];
__device__ float g_pp[NBLK];
__device__ float g_sup[SUPB];
__device__ unsigned g_ctr = 0;

// ---------------------------------------------------------------------------
// Kernel 1: tabulate latent/dlatent. 4 entries per 256-thread block; 64
// threads per entry. Blocks 0..SUPB-1 also fold the supervised loss.
// ---------------------------------------------------------------------------
__global__ __launch_bounds__(256) void build_table(
    const float* __restrict__ W1, const float* __restrict__ b1,
    const float* __restrict__ W2, const float* __restrict__ b2,
    const float* __restrict__ pp, const float* __restrict__ pt,
    const float* __restrict__ icp, const float* __restrict__ ict) {

    __shared__ float s_th[4][64];
    __shared__ float s_dh[4][64];
    __shared__ float s_x[4][16], s_y[4][16];
    __shared__ float s_red[8];

    const int tid = threadIdx.x;
    const int el  = tid >> 6;
    const int j   = tid & 63;
    const int e   = blockIdx.x * 4 + el;

    if (e <= TBL) {
        float tv = (float)e / (float)TBL;
        float w1 = __ldg(W1 + j);
        float u  = fmaf(tv, w1, __ldg(b1 + j));
        float th = tanhf(u);
        s_th[el][j] = th;
        s_dh[el][j] = w1 * (1.f - th * th);
    }
    __syncthreads();

    {
        const int k = tid & 15;
        const int h = (tid >> 4) & 3;
        const int wi = (tid >> 5) & 1;
        float lat = 0.f, dlat = 0.f;
        if (e <= TBL) {
#pragma unroll
            for (int q = 0; q < 16; q++) {
                int jj = h * 16 + q;
                float w2 = __ldg(W2 + jj * 16 + k);
                lat  = fmaf(s_th[el][jj], w2, lat);
                dlat = fmaf(s_dh[el][jj], w2, dlat);
            }
        }
        lat  += __shfl_xor_sync(0xffffffffu, lat,  16);
        dlat += __shfl_xor_sync(0xffffffffu, dlat, 16);
        if (wi == 1 && (tid & 31) < 16) { s_x[el][k] = lat; s_y[el][k] = dlat; }
        __syncthreads();
        if (e <= TBL && wi == 0 && (tid & 31) < 16) {
            g_table[e][2 * k]     = lat + s_x[el][k] + __ldg(b2 + k);
            g_table[e][2 * k + 1] = dlat + s_y[el][k];
        }
    }

    if (blockIdx.x < SUPB) {
        const int ebase = blockIdx.x * 1024 + tid * 4;
        float4 a, t4;
        if (ebase < B_ * P_) {
            a  = __ldg((const float4*)(pp + ebase));
            t4 = __ldg((const float4*)(pt + ebase));
        } else {
            int r = ebase - B_ * P_;
            a  = __ldg((const float4*)(icp + r));
            t4 = __ldg((const float4*)(ict + r));
        }
        float dx = a.x - t4.x, dy = a.y - t4.y, dz = a.z - t4.z, dw = a.w - t4.w;
        float s = fmaf(dx, dx, fmaf(dy, dy, fmaf(dz, dz, dw * dw)));
#pragma unroll
        for (int o = 16; o; o >>= 1) s += __shfl_down_sync(0xffffffffu, s, o);
        if ((tid & 31) == 0) s_red[tid >> 5] = s;
        __syncthreads();
        if (tid == 0) {
            float tot = 0.f;
#pragma unroll
            for (int i = 0; i < 8; i++) tot += s_red[i];
            g_sup[blockIdx.x] = tot;
        }
    }
}

// ---------------------------------------------------------------------------
// Kernel 2: main loss kernel + fused finalize (last-block-done).
// ---------------------------------------------------------------------------
__global__ __launch_bounds__(TPB) void main_kernel(
    const float* __restrict__ t_in,
    const float* __restrict__ x_target,
    const float* __restrict__ params,
    float* __restrict__ out) {

    __shared__ float  s_if[TPB * 2];       // {i_bits, f} per t
    __shared__ float4 s_stage4[TPB * 8];   // XOR-swizzled: row r chunk c at r*8 + (c^(r&7))
    __shared__ float  s_par[P_];
    __shared__ float  s_rd[TPB / 32], s_rp[TPB / 32];
    __shared__ int    s_last;

    const int tid   = threadIdx.x;
    const int b     = blockIdx.x >> 4;
    const int chunk = blockIdx.x & (CHUNKS - 1);
    const int t0    = chunk * TPB;

    // preamble: per-t index/frac precompute (streamed load, evict-first)
    {
        float tv = __ldcs(t_in + (size_t)b * T_ + t0 + tid);
        float p  = tv * (float)TBL;
        int   i  = (int)p;
        i = max(0, min(i, TBL - 1));
        s_if[2 * tid]     = __int_as_float(i);
        s_if[2 * tid + 1] = p - (float)i;
    }
    if (tid < P_) s_par[tid] = __ldg(params + (size_t)b * P_ + tid);
    __syncthreads();

    // ---- Phase A: cooperative vector gather + lerp (table stays L1-hot) ----
    const int kk = tid & 7;
    const int ts = tid >> 3;           // 0..31 ; swizzle term kk^(ts&7) is constant
    const int sw = kk ^ (ts & 7);
#pragma unroll
    for (int pass = 0; pass < 8; ++pass) {
        int r = ts + pass * 32;
        int i = __float_as_int(s_if[2 * r]);
        float f = s_if[2 * r + 1];
        const float4* r0 = (const float4*)g_table[i] + kk;
        float4 lo = __ldg(r0);
        float4 hi = __ldg(r0 + 8);
        float4 res;
        res.x = fmaf(f, hi.x - lo.x, lo.x);
        res.y = fmaf(f, hi.y - lo.y, lo.y);
        res.z = fmaf(f, hi.z - lo.z, lo.z);
        res.w = fmaf(f, hi.w - lo.w, lo.w);
        s_stage4[r * 8 + sw] = res;
    }
    __syncthreads();

    // ---- Phase B: per-t compute ----
    float lat[16], dlat[16];
    {
        const int rs = tid & 7;
#pragma unroll
        for (int d = 0; d < 8; d++) {
            float4 v = s_stage4[tid * 8 + (d ^ rs)];
            lat[2 * d]      = v.x;
            dlat[2 * d]     = v.y;
            lat[2 * d + 1]  = v.z;
            dlat[2 * d + 1] = v.w;
        }
    }

    float x[8], dxv[8];
#pragma unroll
    for (int k = 0; k < 8; k++) {
        float s = lat[8 + k] - s_par[8 + k];
        x[k]   = fmaxf(s, 0.f);
        dxv[k] = (s > 0.f) ? dlat[8 + k] : 0.f;
    }

    float acc_d = 0.f, acc_p = 0.f;

    // data loss (streamed, evict-first: protects L1 table residency)
    const float* xt = x_target + (size_t)b * TWO_N * T_ + t0 + tid;
#pragma unroll
    for (int k = 0; k < 16; k++) {
        float st = (k < 8) ? lat[k] : x[k - 8];
        float d  = st - __ldcs(xt + (size_t)k * T_);
        acc_d = fmaf(d, d, acc_d);
    }

#pragma unroll
    for (int k = 0; k < 8; k++) {
        float pix = 0.f, ga = 0.f;
#pragma unroll
        for (int j = 0; j < 8; j++) {
            pix = fmaf(s_par[16 + k * 8 + j], x[j],   pix);
            ga  = fmaf(s_par[80 + k * 8 + j], lat[j], ga);
        }
        float d1 = dlat[k] - (s_par[k] + pix - lat[k]);
        acc_p = fmaf(d1, d1, acc_p);
        float d2 = dxv[k] - ga * (s_par[8 + k] - x[k]);
        acc_p = fmaf(d2, d2, acc_p);
    }

#pragma unroll
    for (int o = 16; o; o >>= 1) {
        acc_d += __shfl_down_sync(0xffffffffu, acc_d, o);
        acc_p += __shfl_down_sync(0xffffffffu, acc_p, o);
    }
    const int lane = tid & 31, wid = tid >> 5;
    if (lane == 0) { s_rd[wid] = acc_d; s_rp[wid] = acc_p; }
    __syncthreads();
    if (tid == 0) {
        float sd = 0.f, sp = 0.f;
#pragma unroll
        for (int i = 0; i < TPB / 32; i++) { sd += s_rd[i]; sp += s_rp[i]; }
        g_pd[blockIdx.x] = sd;
        g_pp[blockIdx.x] = sp;
        __threadfence();
        unsigned old = atomicAdd(&g_ctr, 1u);
        s_last = (old == NBLK - 1);
    }
    __syncthreads();

    // ---- fused finalize: only the last block, deterministic order ----
    if (s_last) {
        if (tid == 0) g_ctr = 0;               // reset for graph replay
        double sd = 0.0, sp = 0.0;
        for (int i = tid; i < NBLK; i += TPB) {
            sd += (double)g_pd[i];
            sp += (double)g_pp[i];
        }
        double ss = (tid < SUPB) ? (double)g_sup[tid] : 0.0;
        double* r1 = (double*)s_stage4;        // reuse stage smem
        double* r2 = r1 + TPB;
        double* r3 = r2 + TPB;
        r1[tid] = sd; r2[tid] = sp; r3[tid] = ss;
        __syncthreads();
        for (int o = 128; o; o >>= 1) {
            if (tid < o) { r1[tid] += r1[tid + o]; r2[tid] += r2[tid + o]; r3[tid] += r3[tid + o]; }
            __syncthreads();
        }
        if (tid == 0) {
            double res = (r1[0] + r2[0]) / 16777216.0 + r3[0] / 40960.0;
            out[0] = (float)res;
        }
    }
}

// ---------------------------------------------------------------------------
extern "C" void kernel_launch(void* const* d_in, const int* in_sizes, int n_in,
                              void* d_out, int out_size) {
    const float* t   = (const float*)d_in[0];
    const float* xt  = (const float*)d_in[1];
    const float* pp  = (const float*)d_in[2];
    const float* pt  = (const float*)d_in[3];
    const float* icp = (const float*)d_in[4];
    const float* ict = (const float*)d_in[5];
    const float* W1  = (const float*)d_in[6];
    const float* b1  = (const float*)d_in[7];
    const float* W2  = (const float*)d_in[8];
    const float* b2  = (const float*)d_in[9];

    build_table<<<(TBL + 1 + 3) / 4, 256>>>(W1, b1, W2, b2, pp, pt, icp, ict);
    main_kernel<<<NBLK, TPB>>>(t, xt, pp, (float*)d_out);
}

// round 6
// speedup vs baseline: 1.0367x; 1.0367x over previous
#include <cuda_runtime.h>

#define B_    256
#define T_    4096
#define TWO_N 16
#define H_    64
#define P_    144
#define TBL   256
#define TPB   256
#define CHUNKS (T_/TPB)      // 16
#define NBLK  (B_*CHUNKS)    // 4096
#define SUPB  40             // supervised-loss blocks (40*1024 = 40960 elems)

// fp32 table row i: 32 floats = (lat_0,dlat_0,...,lat_15,dlat_15) at t=i/TBL.
// (TBL+1)*128 B = 32.9 KB, L1-resident (streams use __ldcs to avoid eviction).
__device__ float g_table[TBL + 1][32];
__device__ float g_pd[NBLK];
__device__ float g_pp[NBLK];
__device__ float g_sup[SUPB];

// ---------------------------------------------------------------------------
// Kernel 1: tabulate latent/dlatent. 4 entries per 256-thread block; 64
// threads per entry. Blocks 0..SUPB-1 also fold the supervised loss.
// ---------------------------------------------------------------------------
__global__ __launch_bounds__(256) void build_table(
    const float* __restrict__ W1, const float* __restrict__ b1,
    const float* __restrict__ W2, const float* __restrict__ b2,
    const float* __restrict__ pp, const float* __restrict__ pt,
    const float* __restrict__ icp, const float* __restrict__ ict) {

    __shared__ float s_th[4][64];
    __shared__ float s_dh[4][64];
    __shared__ float s_x[4][16], s_y[4][16];
    __shared__ float s_red[8];

    const int tid = threadIdx.x;
    const int el  = tid >> 6;
    const int j   = tid & 63;
    const int e   = blockIdx.x * 4 + el;

    if (e <= TBL) {
        float tv = (float)e / (float)TBL;
        float w1 = __ldg(W1 + j);
        float u  = fmaf(tv, w1, __ldg(b1 + j));
        float th = tanhf(u);
        s_th[el][j] = th;
        s_dh[el][j] = w1 * (1.f - th * th);
    }
    __syncthreads();

    {
        const int k = tid & 15;
        const int h = (tid >> 4) & 3;
        const int wi = (tid >> 5) & 1;
        float lat = 0.f, dlat = 0.f;
        if (e <= TBL) {
#pragma unroll
            for (int q = 0; q < 16; q++) {
                int jj = h * 16 + q;
                float w2 = __ldg(W2 + jj * 16 + k);
                lat  = fmaf(s_th[el][jj], w2, lat);
                dlat = fmaf(s_dh[el][jj], w2, dlat);
            }
        }
        lat  += __shfl_xor_sync(0xffffffffu, lat,  16);
        dlat += __shfl_xor_sync(0xffffffffu, dlat, 16);
        if (wi == 1 && (tid & 31) < 16) { s_x[el][k] = lat; s_y[el][k] = dlat; }
        __syncthreads();
        if (e <= TBL && wi == 0 && (tid & 31) < 16) {
            g_table[e][2 * k]     = lat + s_x[el][k] + __ldg(b2 + k);
            g_table[e][2 * k + 1] = dlat + s_y[el][k];
        }
    }

    if (blockIdx.x < SUPB) {
        const int ebase = blockIdx.x * 1024 + tid * 4;
        float4 a, t4;
        if (ebase < B_ * P_) {
            a  = __ldg((const float4*)(pp + ebase));
            t4 = __ldg((const float4*)(pt + ebase));
        } else {
            int r = ebase - B_ * P_;
            a  = __ldg((const float4*)(icp + r));
            t4 = __ldg((const float4*)(ict + r));
        }
        float dx = a.x - t4.x, dy = a.y - t4.y, dz = a.z - t4.z, dw = a.w - t4.w;
        float s = fmaf(dx, dx, fmaf(dy, dy, fmaf(dz, dz, dw * dw)));
#pragma unroll
        for (int o = 16; o; o >>= 1) s += __shfl_down_sync(0xffffffffu, s, o);
        if ((tid & 31) == 0) s_red[tid >> 5] = s;
        __syncthreads();
        if (tid == 0) {
            float tot = 0.f;
#pragma unroll
            for (int i = 0; i < 8; i++) tot += s_red[i];
            g_sup[blockIdx.x] = tot;
        }
    }
}

// ---------------------------------------------------------------------------
// Kernel 2: main loss kernel. One block = (batch b, 256 t's). 5 blocks/SM.
// ---------------------------------------------------------------------------
__global__ __launch_bounds__(TPB, 5) void main_kernel(
    const float* __restrict__ t_in,
    const float* __restrict__ x_target,
    const float* __restrict__ params) {

    __shared__ float  s_if[TPB * 2];       // {i_bits, f} per t
    __shared__ float4 s_stage4[TPB * 8];   // XOR-swizzled: row r chunk c at r*8 + (c^(r&7))
    __shared__ float  s_par[P_];
    __shared__ float  s_rd[TPB / 32], s_rp[TPB / 32];

    const int tid   = threadIdx.x;
    const int b     = blockIdx.x >> 4;
    const int chunk = blockIdx.x & (CHUNKS - 1);
    const int t0    = chunk * TPB;

    // preamble: per-t index/frac precompute (streamed load, evict-first)
    {
        float tv = __ldcs(t_in + (size_t)b * T_ + t0 + tid);
        float p  = tv * (float)TBL;
        int   i  = (int)p;
        i = max(0, min(i, TBL - 1));
        s_if[2 * tid]     = __int_as_float(i);
        s_if[2 * tid + 1] = p - (float)i;
    }
    if (tid < P_) s_par[tid] = __ldg(params + (size_t)b * P_ + tid);
    __syncthreads();

    // ---- Phase A: cooperative vector gather + lerp (table L1-hot) ----
    const int kk = tid & 7;
    const int ts = tid >> 3;           // 0..31 ; swizzle term is per-thread constant
    const int sw = kk ^ (ts & 7);
#pragma unroll
    for (int pass = 0; pass < 8; ++pass) {
        int r = ts + pass * 32;
        int i = __float_as_int(s_if[2 * r]);
        float f = s_if[2 * r + 1];
        const float4* r0 = (const float4*)g_table[i] + kk;
        float4 lo = __ldg(r0);
        float4 hi = __ldg(r0 + 8);
        float4 res;
        res.x = fmaf(f, hi.x - lo.x, lo.x);
        res.y = fmaf(f, hi.y - lo.y, lo.y);
        res.z = fmaf(f, hi.z - lo.z, lo.z);
        res.w = fmaf(f, hi.w - lo.w, lo.w);
        s_stage4[r * 8 + sw] = res;
    }
    __syncthreads();

    // ---- Phase B: per-t compute (register-lean: x/dxv overwrite in place) ----
    float lat[16], dlat[16];
    {
        const int rs = tid & 7;
#pragma unroll
        for (int d = 0; d < 8; d++) {
            float4 v = s_stage4[tid * 8 + (d ^ rs)];
            lat[2 * d]      = v.x;
            dlat[2 * d]     = v.y;
            lat[2 * d + 1]  = v.z;
            dlat[2 * d + 1] = v.w;
        }
    }

    // observables in place: lat[8+k] <- x_k = relu(q-mu); dlat[8+k] <- jvp
#pragma unroll
    for (int k = 0; k < 8; k++) {
        float s = lat[8 + k] - s_par[8 + k];
        lat[8 + k]  = fmaxf(s, 0.f);
        dlat[8 + k] = (s > 0.f) ? dlat[8 + k] : 0.f;
    }

    float acc_p = 0.f;
    // physics loss first (kills dlat before the data-loss loads)
#pragma unroll
    for (int k = 0; k < 8; k++) {
        float pix = 0.f, ga = 0.f;
#pragma unroll
        for (int j = 0; j < 8; j++) {
            pix = fmaf(s_par[16 + k * 8 + j], lat[8 + j], pix);
            ga  = fmaf(s_par[80 + k * 8 + j], lat[j],     ga);
        }
        float d1 = dlat[k] - (s_par[k] + pix - lat[k]);
        acc_p = fmaf(d1, d1, acc_p);
        float d2 = dlat[8 + k] - ga * (s_par[8 + k] - lat[8 + k]);
        acc_p = fmaf(d2, d2, acc_p);
    }

    // data loss: state == lat[0..15] now (streamed loads, 16-deep MLP)
    float acc_d = 0.f;
    const float* xt = x_target + (size_t)b * TWO_N * T_ + t0 + tid;
#pragma unroll
    for (int k = 0; k < 16; k++) {
        float d = lat[k] - __ldcs(xt + (size_t)k * T_);
        acc_d = fmaf(d, d, acc_d);
    }

    // ---- block reduction ----
#pragma unroll
    for (int o = 16; o; o >>= 1) {
        acc_d += __shfl_down_sync(0xffffffffu, acc_d, o);
        acc_p += __shfl_down_sync(0xffffffffu, acc_p, o);
    }
    const int lane = tid & 31, wid = tid >> 5;
    if (lane == 0) { s_rd[wid] = acc_d; s_rp[wid] = acc_p; }
    __syncthreads();
    if (tid == 0) {
        float sd = 0.f, sp = 0.f;
#pragma unroll
        for (int i = 0; i < TPB / 32; i++) { sd += s_rd[i]; sp += s_rp[i]; }
        g_pd[blockIdx.x] = sd;
        g_pp[blockIdx.x] = sp;
    }
}

// ---------------------------------------------------------------------------
// Kernel 3: finalize — deterministic double sums of tiny partial arrays.
// ---------------------------------------------------------------------------
__global__ void finalize(float* __restrict__ out) {
    const int tid = threadIdx.x;
    double sd = 0.0, sp = 0.0;
    for (int i = tid; i < NBLK; i += 256) {
        sd += (double)g_pd[i];
        sp += (double)g_pp[i];
    }
    double ss = (tid < SUPB) ? (double)g_sup[tid] : 0.0;
    __shared__ double r1[256], r2[256], r3[256];
    r1[tid] = sd; r2[tid] = sp; r3[tid] = ss;
    __syncthreads();
    for (int o = 128; o; o >>= 1) {
        if (tid < o) { r1[tid] += r1[tid + o]; r2[tid] += r2[tid + o]; r3[tid] += r3[tid + o]; }
        __syncthreads();
    }
    if (tid == 0) {
        double res = (r1[0] + r2[0]) / 16777216.0 + r3[0] / 40960.0;
        out[0] = (float)res;
    }
}

// ---------------------------------------------------------------------------
extern "C" void kernel_launch(void* const* d_in, const int* in_sizes, int n_in,
                              void* d_out, int out_size) {
    const float* t   = (const float*)d_in[0];
    const float* xt  = (const float*)d_in[1];
    const float* pp  = (const float*)d_in[2];
    const float* pt  = (const float*)d_in[3];
    const float* icp = (const float*)d_in[4];
    const float* ict = (const float*)d_in[5];
    const float* W1  = (const float*)d_in[6];
    const float* b1  = (const float*)d_in[7];
    const float* W2  = (const float*)d_in[8];
    const float* b2  = (const float*)d_in[9];

    build_table<<<(TBL + 1 + 3) / 4, 256>>>(W1, b1, W2, b2, pp, pt, icp, ict);
    main_kernel<<<NBLK, TPB>>>(t, xt, pp);
    finalize<<<1, 256>>>((float*)d_out);
}